// round 14
// baseline (speedup 1.0000x reference)
#include <cuda_runtime.h>
#include <cuda_fp16.h>
#include <math.h>
#include <cstdint>

#define NBATCH 8
#define LSEQ   4096
#define SSEQ   4096
#define CDIM   256
#define HHEADS 8
#define DHEAD  32
#define MROWS  (NBATCH * LSEQ)

#define MQ  0
#define MKV 1
#define MM  2
#define MH  3
#define MO  4

__device__ float g_Ksum[NBATCH * CDIM];
__device__ float g_KV  [NBATCH * HHEADS * DHEAD * DHEAD];

__device__ __align__(256) __half g_Qh   [MROWS * CDIM];
__device__ __align__(256) __half g_Qpos [MROWS * CDIM];
__device__ __align__(256) __half g_Kpos [MROWS * CDIM];
__device__ __align__(256) __half g_Vrot [MROWS * CDIM];
__device__ __align__(256) __half g_cat  [MROWS * 512];   // [x | msg]
__device__ __align__(256) __half g_sb   [MROWS * CDIM];
__device__ __align__(256) __half g_Qrb  [MROWS * CDIM];
__device__ __align__(256) __half g_hb   [MROWS * 512];
__device__ __align__(256) __half g_Wq_h [256 * 256], g_Wq_l [256 * 256];
__device__ __align__(256) __half g_Wkv_h[256 * 512], g_Wkv_l[256 * 512];
__device__ __align__(256) __half g_Wm_h [256 * 256], g_Wm_l [256 * 256];
__device__ __align__(256) __half g_W1_h [512 * 512], g_W1_l [512 * 512];
__device__ __align__(256) __half g_W2_h [512 * 256], g_W2_l [512 * 256];

__device__ __forceinline__ uint32_t smem_u32(const void* p) {
    uint32_t a;
    asm("{ .reg .u64 t; cvta.to.shared.u64 t, %1; cvt.u32.u64 %0, t; }" : "=r"(a) : "l"(p));
    return a;
}
__device__ __forceinline__ void ldsm4(uint32_t* r, uint32_t addr) {
    asm volatile("ldmatrix.sync.aligned.m8n8.x4.shared.b16 {%0,%1,%2,%3}, [%4];"
        : "=r"(r[0]), "=r"(r[1]), "=r"(r[2]), "=r"(r[3]) : "r"(addr));
}
__device__ __forceinline__ void ldsm4t(uint32_t* r, uint32_t addr) {
    asm volatile("ldmatrix.sync.aligned.m8n8.x4.trans.shared.b16 {%0,%1,%2,%3}, [%4];"
        : "=r"(r[0]), "=r"(r[1]), "=r"(r[2]), "=r"(r[3]) : "r"(addr));
}
__device__ __forceinline__ void mma_f16(float& d0, float& d1, float& d2, float& d3,
                                        const uint32_t* a, uint32_t b0, uint32_t b1) {
    asm volatile("mma.sync.aligned.m16n8k16.row.col.f32.f16.f16.f32 "
        "{%0,%1,%2,%3}, {%4,%5,%6,%7}, {%8,%9}, {%0,%1,%2,%3};"
        : "+f"(d0), "+f"(d1), "+f"(d2), "+f"(d3)
        : "r"(a[0]), "r"(a[1]), "r"(a[2]), "r"(a[3]), "r"(b0), "r"(b1));
}
#define CP16(dst, src) asm volatile("cp.async.cg.shared.global [%0], [%1], 16;" :: "r"(dst), "l"(src))
#define CP_COMMIT()    asm volatile("cp.async.commit_group;")
#define CP_WAIT1()     asm volatile("cp.async.wait_group 1;")
#define CP_WAIT0()     asm volatile("cp.async.wait_group 0;")

__device__ __forceinline__ void split_h(float v, __half& h, __half& l) {
    h = __float2half(v);
    l = __float2half(v - __half2float(h));
}
__device__ __forceinline__ float elu1(float v) {
    return v > 0.f ? v + 1.f : __expf(v);
}

// ---------------- conversion kernels ----------------
__global__ void xcat(const float* __restrict__ x) {
    int i = (blockIdx.x * 256 + threadIdx.x) * 4;
    if (i >= MROWS * CDIM) return;
    float4 v = *(const float4*)(x + i);
    int row = i >> 8, col = i & 255;
    __half* d = g_cat + (size_t)row * 512 + col;
    *(__half2*)(d)     = __half2{__float2half(v.x), __float2half(v.y)};
    *(__half2*)(d + 2) = __half2{__float2half(v.z), __float2half(v.w)};
}
__global__ void aconv(const float* __restrict__ s, __half* __restrict__ d, int n) {
    int i = (blockIdx.x * 256 + threadIdx.x) * 4;
    if (i >= n) return;
    float4 v = *(const float4*)(s + i);
    *(__half2*)(d + i)     = __half2{__float2half(v.x), __float2half(v.y)};
    *(__half2*)(d + i + 2) = __half2{__float2half(v.z), __float2half(v.w)};
}
__global__ void wsplit(const float* __restrict__ s, __half* __restrict__ dh,
                       __half* __restrict__ dl, int n) {
    int i = blockIdx.x * 256 + threadIdx.x;
    if (i >= n) return;
    split_h(s[i], dh[i], dl[i]);
}
__global__ void wkvconv(const float* __restrict__ Wk, const float* __restrict__ Wv) {
    int i = blockIdx.x * 256 + threadIdx.x;
    if (i >= 256 * 512) return;
    int k = i >> 9, nn = i & 511;
    float v = (nn < 256) ? Wk[k * 256 + nn] : Wv[k * 256 + nn - 256];
    split_h(v, g_Wkv_h[i], g_Wkv_l[i]);
}
__global__ void zero_kernel() {
    int i = blockIdx.x * blockDim.x + threadIdx.x;
    if (i < NBATCH * HHEADS * DHEAD * DHEAD) g_KV[i] = 0.f;
    if (i < NBATCH * CDIM) g_Ksum[i] = 0.f;
}

// ============ small GEMM: CTA 128x128x32, warp 64x32, 2 CTAs/SM ============
#define SA   40
#define SBs  136
#define A_ST 10240u
#define BsST 8704u
#define STGs 27648u
#define SMSZ_S (3u * STGs)     // 82944

template <int MODE>
__global__ __launch_bounds__(256, 2)
void mma_small(const float* __restrict__ pe)
{
    constexpr int KTOT  = (MODE == MH) ? 512 : 256;
    constexpr int NCOLS = (MODE == MQ) ? 256 : 512;
    constexpr int ASTR  = (MODE == MKV) ? 256 : 512;
    constexpr int S = KTOT / 32;
    extern __shared__ char sm[];
    const uint32_t smb = smem_u32(sm);
    const int tid = threadIdx.x;
    const int wid = tid >> 5, lane = tid & 31;
    const int wm = wid >> 2, wn = wid & 3;
    const int n0 = blockIdx.x * 128;
    const int m0 = blockIdx.y * 128;

    const __half* Bh = (MODE == MQ) ? g_Wq_h : (MODE == MKV) ? g_Wkv_h : g_W1_h;
    const __half* Bl = (MODE == MQ) ? g_Wq_l : (MODE == MKV) ? g_Wkv_l : g_W1_l;
    const __half* A0 = (MODE == MKV) ? g_sb : g_cat;

    const __half* gA0 = A0 + (size_t)(m0 + (tid >> 2)) * ASTR + (tid & 3) * 8;
    const __half* gA1 = gA0 + 64 * ASTR;
    const uint32_t dA0 = (tid >> 2) * 80u + (tid & 3) * 16u;
    const uint32_t dA1 = dA0 + 64u * 80u;
    const ptrdiff_t bdelta = Bl - Bh;
    const __half* gB0 = Bh + (size_t)(tid >> 4) * NCOLS + n0 + (tid & 15) * 8;
    const uint32_t dB0 = (tid >> 4) * 272u + (tid & 15) * 16u;

    auto cpA = [&](int stg) {
        uint32_t base = smb + stg * STGs;
        CP16(base + dA0, gA0);
        CP16(base + dA1, gA1);
        gA0 += 32; gA1 += 32;
    };
    auto cpB = [&](int stg) {
        uint32_t base = smb + stg * STGs + A_ST;
        const __half* g = gB0;
#pragma unroll
        for (int i = 0; i < 2; i++) {
            uint32_t d = base + dB0 + i * (16u * 272u);
            CP16(d, g);
            CP16(d + BsST, g + bdelta);
            g += 16 * NCOLS;
        }
        gB0 += 32 * NCOLS;
    };

    float acc[4][4][4];
#pragma unroll
    for (int a = 0; a < 4; a++)
#pragma unroll
        for (int b = 0; b < 4; b++)
#pragma unroll
            for (int c = 0; c < 4; c++) acc[a][b][c] = 0.f;

    const uint32_t aoffBase = ((wm * 64 + (lane & 15)) * SA + (lane >> 4) * 8) * 2u;
    const uint32_t boffBase = (((lane & 15)) * SBs + wn * 32 + (lane >> 4) * 8) * 2u;

    auto compute = [&](int stg) {
        const uint32_t aB = smb + stg * STGs + aoffBase;
        const uint32_t bH = smb + stg * STGs + A_ST + boffBase;
        const uint32_t bL = bH + BsST;
#pragma unroll
        for (int k16 = 0; k16 < 32; k16 += 16) {
            uint32_t af[4][4];
#pragma unroll
            for (int mt = 0; mt < 4; mt++)
                ldsm4(af[mt], aB + (mt * 16 * SA + k16) * 2u);
#pragma unroll
            for (int nt = 0; nt < 2; nt++) {
                uint32_t bh[4], bl[4];
                uint32_t o = (k16 * SBs + nt * 16) * 2u;
                ldsm4t(bh, bH + o);
                ldsm4t(bl, bL + o);
#pragma unroll
                for (int mt = 0; mt < 4; mt++) {
                    float* d0 = acc[mt][nt * 2];
                    float* d1 = acc[mt][nt * 2 + 1];
                    mma_f16(d0[0], d0[1], d0[2], d0[3], af[mt], bh[0], bh[1]);
                    mma_f16(d1[0], d1[1], d1[2], d1[3], af[mt], bh[2], bh[3]);
                    mma_f16(d0[0], d0[1], d0[2], d0[3], af[mt], bl[0], bl[1]);
                    mma_f16(d1[0], d1[1], d1[2], d1[3], af[mt], bl[2], bl[3]);
                }
            }
        }
    };

    cpA(0); cpB(0); CP_COMMIT();
    cpA(1); cpB(1); CP_COMMIT();
#pragma unroll 1
    for (int s = 0; s < S; s++) {
        if (s < S - 1) { CP_WAIT1(); } else { CP_WAIT0(); }
        __syncthreads();
        if (s + 2 < S) {
            int stg = (s + 2) % 3;
            cpA(stg); cpB(stg); CP_COMMIT();
        }
        compute(s % 3);
    }

    // ---- epilogue ----
    const int Mbase = m0 + wm * 64;
    const int Nbase = n0 + wn * 32;
    const int rr = lane >> 2;
    const int cc = (lane & 3) * 2;

    float csum[4][2];
    const bool kpath = (MODE == MKV) && (n0 < 256);
    if (kpath) {
#pragma unroll
        for (int a = 0; a < 4; a++) { csum[a][0] = 0.f; csum[a][1] = 0.f; }
        __syncthreads();
        if (tid < 128) ((float*)sm)[tid] = 0.f;
        __syncthreads();
    }

#pragma unroll
    for (int mt = 0; mt < 4; mt++)
#pragma unroll
        for (int n8 = 0; n8 < 4; n8++)
#pragma unroll
            for (int h2 = 0; h2 < 2; h2++) {
                int row = Mbase + mt * 16 + rr + h2 * 8;
                int col = Nbase + n8 * 8 + cc;
                float d0 = acc[mt][n8][2 * h2];
                float d1 = acc[mt][n8][2 * h2 + 1];
                if (MODE == MQ) {
                    float4 pv = *(const float4*)(pe + ((size_t)row * 256 + col) * 2);
                    *(__half2*)(g_Qpos + (size_t)row * 256 + col) = __half2{
                        __float2half(d0 * pv.x - d1 * pv.y),
                        __float2half(d1 * pv.z + d0 * pv.w)};
                    *(__half2*)(g_Qh + (size_t)row * 256 + col) = __half2{
                        __float2half(elu1(d0)), __float2half(elu1(d1))};
                } else if (MODE == MKV) {
                    int pc = kpath ? col : col - 256;
                    float4 pv = *(const float4*)(pe + ((size_t)row * 256 + pc) * 2);
                    float re = d0 * pv.x - d1 * pv.y;
                    float ro = d1 * pv.z + d0 * pv.w;
                    if (kpath) {
                        *(__half2*)(g_Kpos + (size_t)row * 256 + col) = __half2{
                            __float2half(re), __float2half(ro)};
                        csum[n8][0] += elu1(d0);
                        csum[n8][1] += elu1(d1);
                    } else {
                        *(__half2*)(g_Vrot + (size_t)row * 256 + pc) = __half2{
                            __float2half(re), __float2half(ro)};
                    }
                } else {  // MH
                    *(__half2*)(g_hb + (size_t)row * 512 + col) = __half2{
                        __float2half(fmaxf(d0, 0.f)), __float2half(fmaxf(d1, 0.f))};
                }
            }

    if (kpath) {
        float* scs = (float*)sm;
#pragma unroll
        for (int n8 = 0; n8 < 4; n8++) {
            atomicAdd(&scs[wn * 32 + n8 * 8 + cc],     csum[n8][0]);
            atomicAdd(&scs[wn * 32 + n8 * 8 + cc + 1], csum[n8][1]);
        }
        __syncthreads();
        if (tid < 128) {
            int n = m0 / SSEQ;
            atomicAdd(&g_Ksum[n * CDIM + n0 + tid], scs[tid]);
        }
    }
}

// ========= big GEMM: CTA 128x256x32, 16 warps (2x8) of 64x32, LN fused =====
#define SB 264
#define B_ST 16896u
#define STG  44032u
#define SMSZ (3u * STG)        // 132096

template <int MODE>
__global__ __launch_bounds__(512, 1)
void mma_big(const float* __restrict__ lng, const float* __restrict__ lnb,
             const float* __restrict__ xres, float* __restrict__ outx)
{
    constexpr int KTOT  = (MODE == MO) ? 512 : 256;
    constexpr int ASTR  = (MODE == MO) ? 512 : 256;
    constexpr int S = KTOT / 32;
    extern __shared__ char sm[];
    const uint32_t smb = smem_u32(sm);
    const int tid = threadIdx.x;
    const int wid = tid >> 5, lane = tid & 31;
    const int wm = wid >> 3, wn = wid & 7;     // 2x8 warp grid, 64x32 tiles
    const int m0 = blockIdx.y * 128;

    const __half* Bh = (MODE == MM) ? g_Wm_h : g_W2_h;
    const __half* Bl = (MODE == MM) ? g_Wm_l : g_W2_l;
    const __half* A0 = (MODE == MM) ? g_Qrb : g_hb;

    const __half* gA0 = A0 + (size_t)(m0 + (tid >> 2)) * ASTR + (tid & 3) * 8;
    const uint32_t dA0 = (tid >> 2) * 80u + (tid & 3) * 16u;
    const ptrdiff_t bdelta = Bl - Bh;
    const __half* gB0 = Bh + (size_t)(tid >> 5) * 256 + (tid & 31) * 8;
    const uint32_t dB0 = (tid >> 5) * 528u + (tid & 31) * 16u;

    auto cpA = [&](int stg) {
        CP16(smb + stg * STG + dA0, gA0);
        gA0 += 32;
    };
    auto cpB = [&](int stg) {
        uint32_t base = smb + stg * STG + A_ST;
        const __half* g = gB0;
#pragma unroll
        for (int i = 0; i < 2; i++) {
            uint32_t d = base + dB0 + i * (16u * 528u);
            CP16(d, g);
            CP16(d + B_ST, g + bdelta);
            g += 16 * 256;
        }
        gB0 += 32 * 256;
    };

    float acc[4][4][4];
#pragma unroll
    for (int a = 0; a < 4; a++)
#pragma unroll
        for (int b = 0; b < 4; b++)
#pragma unroll
            for (int c = 0; c < 4; c++) acc[a][b][c] = 0.f;

    const uint32_t aoffBase = ((wm * 64 + (lane & 15)) * SA + (lane >> 4) * 8) * 2u;
    const uint32_t boffBase = (((lane & 15)) * SB + wn * 32 + (lane >> 4) * 8) * 2u;

    auto compute = [&](int stg) {
        const uint32_t aB = smb + stg * STG + aoffBase;
        const uint32_t bH = smb + stg * STG + A_ST + boffBase;
        const uint32_t bL = bH + B_ST;
#pragma unroll
        for (int k16 = 0; k16 < 32; k16 += 16) {
            uint32_t af[4][4];
#pragma unroll
            for (int mt = 0; mt < 4; mt++)
                ldsm4(af[mt], aB + (mt * 16 * SA + k16) * 2u);
#pragma unroll
            for (int nt = 0; nt < 2; nt++) {
                uint32_t bh[4], bl[4];
                uint32_t o = (k16 * SB + nt * 16) * 2u;
                ldsm4t(bh, bH + o);
                ldsm4t(bl, bL + o);
#pragma unroll
                for (int mt = 0; mt < 4; mt++) {
                    float* d0 = acc[mt][nt * 2];
                    float* d1 = acc[mt][nt * 2 + 1];
                    mma_f16(d0[0], d0[1], d0[2], d0[3], af[mt], bh[0], bh[1]);
                    mma_f16(d1[0], d1[1], d1[2], d1[3], af[mt], bh[2], bh[3]);
                    mma_f16(d0[0], d0[1], d0[2], d0[3], af[mt], bl[0], bl[1]);
                    mma_f16(d1[0], d1[1], d1[2], d1[3], af[mt], bl[2], bl[3]);
                }
            }
        }
    };

    cpA(0); cpB(0); CP_COMMIT();
    cpA(1); cpB(1); CP_COMMIT();
#pragma unroll 1
    for (int s = 0; s < S; s++) {
        if (s < S - 1) { CP_WAIT1(); } else { CP_WAIT0(); }
        __syncthreads();
        if (s + 2 < S) {
            int stg = (s + 2) % 3;
            cpA(stg); cpB(stg); CP_COMMIT();
        }
        compute(s % 3);
    }

    // ---- fused LayerNorm epilogue (CTA owns full 256-col rows) ----
    const int Nbase = wn * 32;
    const int rr = lane >> 2;
    const int cc = (lane & 3) * 2;
    float* rs = (float*)sm;    // [128] sum, [128] sumsq
    __syncthreads();
    if (tid < 256) rs[tid] = 0.f;
    __syncthreads();
#pragma unroll
    for (int mt = 0; mt < 4; mt++)
#pragma unroll
        for (int h2 = 0; h2 < 2; h2++) {
            int lrow = wm * 64 + mt * 16 + rr + h2 * 8;
            float s = 0.f, ss = 0.f;
#pragma unroll
            for (int n8 = 0; n8 < 4; n8++) {
                float d0 = acc[mt][n8][2 * h2];
                float d1 = acc[mt][n8][2 * h2 + 1];
                s += d0 + d1;
                ss += d0 * d0 + d1 * d1;
            }
            atomicAdd(&rs[lrow], s);
            atomicAdd(&rs[128 + lrow], ss);
        }
    __syncthreads();
#pragma unroll
    for (int mt = 0; mt < 4; mt++)
#pragma unroll
        for (int h2 = 0; h2 < 2; h2++) {
            int lrow = wm * 64 + mt * 16 + rr + h2 * 8;
            int row = m0 + lrow;
            float mean = rs[lrow] * (1.f / 256.f);
            float var  = rs[128 + lrow] * (1.f / 256.f) - mean * mean;
            float rstd = rsqrtf(var + 1e-5f);
#pragma unroll
            for (int n8 = 0; n8 < 4; n8++) {
                int col = Nbase + n8 * 8 + cc;
                float v0 = (acc[mt][n8][2 * h2]     - mean) * rstd * lng[col] + lnb[col];
                float v1 = (acc[mt][n8][2 * h2 + 1] - mean) * rstd * lng[col + 1] + lnb[col + 1];
                if (MODE == MM) {
                    *(__half2*)(g_cat + (size_t)row * 512 + 256 + col) = __half2{
                        __float2half(v0), __float2half(v1)};
                } else {
                    const float* xr = xres + (size_t)row * 256 + col;
                    *(float2*)(outx + (size_t)row * 256 + col) =
                        make_float2(v0 + xr[0], v1 + xr[1]);
                }
            }
        }
}

// ---------------- KV einsum ----------------
__global__ __launch_bounds__(256) void kv_kernel() {
    const int nh = blockIdx.x;
    const int n = nh / HHEADS, h = nh % HHEADS;
    const int s0 = blockIdx.y * (SSEQ / 8);
    __shared__ float sK[16][DHEAD];
    __shared__ float sV[16][DHEAD];
    const int t = threadIdx.x;
    const int d = t >> 3, vb = (t & 7) * 4;
    float a0 = 0.f, a1 = 0.f, a2 = 0.f, a3 = 0.f;
    for (int sc = 0; sc < SSEQ / 8; sc += 16) {
#pragma unroll
        for (int rep = 0; rep < 2; rep++) {
            int idx = t + rep * 256;
            int sr = idx >> 5, c = idx & 31;
            int off = (n * SSEQ + s0 + sc + sr) * CDIM + h * DHEAD + c;
            sK[sr][c] = __half2float(g_Kpos[off]);
            sV[sr][c] = __half2float(g_Vrot[off]);
        }
        __syncthreads();
#pragma unroll
        for (int sr = 0; sr < 16; sr++) {
            float kd = sK[sr][d];
            float4 v = *(const float4*)&sV[sr][vb];
            a0 += kd * v.x; a1 += kd * v.y; a2 += kd * v.z; a3 += kd * v.w;
        }
        __syncthreads();
    }
    float* dst = &g_KV[((n * HHEADS + h) * DHEAD + d) * DHEAD + vb];
    atomicAdd(dst + 0, a0); atomicAdd(dst + 1, a1);
    atomicAdd(dst + 2, a2); atomicAdd(dst + 3, a3);
}

// ------- queried -------
__global__ __launch_bounds__(256) void queried_kernel() {
    const int n  = blockIdx.x >> 5;
    const int l0 = (blockIdx.x & 31) * 128;
    const int h = threadIdx.x >> 5, lane = threadIdx.x & 31;
    float kvreg[32];
    const float* kvb = &g_KV[(n * HHEADS + h) * DHEAD * DHEAD];
#pragma unroll
    for (int dd = 0; dd < 32; dd++) kvreg[dd] = kvb[dd * 32 + lane];
    const float ks = g_Ksum[n * CDIM + h * 32 + lane];
#pragma unroll 2
    for (int r = 0; r < 128; r++) {
        size_t base = ((size_t)(n * LSEQ + l0 + r)) * CDIM + h * 32;
        float q  = __half2float(g_Qh[base + lane]);
        float qp = __half2float(g_Qpos[base + lane]);
        float p = q * ks;
#pragma unroll
        for (int o = 16; o; o >>= 1) p += __shfl_xor_sync(0xffffffffu, p, o);
        float z = 1.0f / (p + 1e-6f);
        float s1 = 0.f;
#pragma unroll
        for (int dd = 0; dd < 32; dd++)
            s1 += __shfl_sync(0xffffffffu, qp, dd) * kvreg[dd];
        g_Qrb[base + lane] = __float2half(s1 * z);
    }
}

// ---------------- launch ----------------
extern "C" void kernel_launch(void* const* d_in, const int* in_sizes, int n_in,
                              void* d_out, int out_size)
{
    const float* x      = (const float*)d_in[0];
    const float* source = (const float*)d_in[1];
    const float* x_pe   = (const float*)d_in[2];
    const float* s_pe   = (const float*)d_in[3];
    const float* Wq     = (const float*)d_in[4];
    const float* Wk     = (const float*)d_in[5];
    const float* Wv     = (const float*)d_in[6];
    const float* Wm     = (const float*)d_in[7];
    const float* W1     = (const float*)d_in[8];
    const float* W2     = (const float*)d_in[9];
    const float* ln1_g  = (const float*)d_in[10];
    const float* ln1_b  = (const float*)d_in[11];
    const float* ln2_g  = (const float*)d_in[12];
    const float* ln2_b  = (const float*)d_in[13];
    float* out = (float*)d_out;

    cudaFuncSetAttribute(mma_small<MQ>,  cudaFuncAttributeMaxDynamicSharedMemorySize, SMSZ_S);
    cudaFuncSetAttribute(mma_small<MKV>, cudaFuncAttributeMaxDynamicSharedMemorySize, SMSZ_S);
    cudaFuncSetAttribute(mma_small<MH>,  cudaFuncAttributeMaxDynamicSharedMemorySize, SMSZ_S);
    cudaFuncSetAttribute(mma_big<MM>,    cudaFuncAttributeMaxDynamicSharedMemorySize, SMSZ);
    cudaFuncSetAttribute(mma_big<MO>,    cudaFuncAttributeMaxDynamicSharedMemorySize, SMSZ);

    __half *sb, *wqh, *wql, *wmh, *wml, *w1h, *w1l, *w2h, *w2l;
    cudaGetSymbolAddress((void**)&sb, g_sb);
    cudaGetSymbolAddress((void**)&wqh, g_Wq_h); cudaGetSymbolAddress((void**)&wql, g_Wq_l);
    cudaGetSymbolAddress((void**)&wmh, g_Wm_h); cudaGetSymbolAddress((void**)&wml, g_Wm_l);
    cudaGetSymbolAddress((void**)&w1h, g_W1_h); cudaGetSymbolAddress((void**)&w1l, g_W1_l);
    cudaGetSymbolAddress((void**)&w2h, g_W2_h); cudaGetSymbolAddress((void**)&w2l, g_W2_l);

    xcat<<<MROWS * CDIM / 1024, 256>>>(x);
    wsplit<<<256 * 256 / 256, 256>>>(Wq, wqh, wql, 256 * 256);
    zero_kernel<<<256, 256>>>();
    mma_small<MQ><<<dim3(2, MROWS / 128), 256, SMSZ_S>>>(x_pe);
    aconv<<<MROWS * CDIM / 1024, 256>>>(source, sb, MROWS * CDIM);
    wkvconv<<<256 * 512 / 256, 256>>>(Wk, Wv);
    mma_small<MKV><<<dim3(4, MROWS / 128), 256, SMSZ_S>>>(s_pe);

    kv_kernel<<<dim3(NBATCH * HHEADS, 8), 256>>>();
    queried_kernel<<<NBATCH * (LSEQ / 128), 256>>>();

    wsplit<<<256 * 256 / 256, 256>>>(Wm, wmh, wml, 256 * 256);
    mma_big<MM><<<dim3(1, MROWS / 128), 512, SMSZ>>>(ln1_g, ln1_b, nullptr, nullptr);

    wsplit<<<512 * 512 / 256, 256>>>(W1, w1h, w1l, 512 * 512);
    mma_small<MH><<<dim3(4, MROWS / 128), 256, SMSZ_S>>>(nullptr);
    wsplit<<<512 * 256 / 256, 256>>>(W2, w2h, w2l, 512 * 256);
    mma_big<MO><<<dim3(1, MROWS / 128), 512, SMSZ>>>(ln2_g, ln2_b, x, out);
}

// round 15
// speedup vs baseline: 1.0014x; 1.0014x over previous
#include <cuda_runtime.h>
#include <cuda_fp16.h>
#include <math.h>
#include <cstdint>

#define NBATCH 8
#define LSEQ   4096
#define SSEQ   4096
#define CDIM   256
#define HHEADS 8
#define DHEAD  32
#define MROWS  (NBATCH * LSEQ)

#define MQ  0
#define MKV 1
#define MM  2
#define MH  3
#define MO  4

__device__ float g_Ksum[NBATCH * CDIM];
__device__ float g_KV  [NBATCH * HHEADS * DHEAD * DHEAD];

__device__ __align__(256) __half g_Qh   [MROWS * CDIM];
__device__ __align__(256) __half g_Qpos [MROWS * CDIM];
__device__ __align__(256) __half g_Kpos [MROWS * CDIM];
__device__ __align__(256) __half g_Vrot [MROWS * CDIM];
__device__ __align__(256) __half g_cat  [MROWS * 512];   // [x | msg]
__device__ __align__(256) __half g_sb   [MROWS * CDIM];
__device__ __align__(256) __half g_Qrb  [MROWS * CDIM];
__device__ __align__(256) __half g_hb   [MROWS * 512];
__device__ __align__(256) __half g_Wq_h [256 * 256], g_Wq_l [256 * 256];
__device__ __align__(256) __half g_Wkv_h[256 * 512], g_Wkv_l[256 * 512];
__device__ __align__(256) __half g_Wm_h [256 * 256], g_Wm_l [256 * 256];
__device__ __align__(256) __half g_W1_h [512 * 512], g_W1_l [512 * 512];
__device__ __align__(256) __half g_W2_h [512 * 256], g_W2_l [512 * 256];

__device__ __forceinline__ uint32_t smem_u32(const void* p) {
    uint32_t a;
    asm("{ .reg .u64 t; cvta.to.shared.u64 t, %1; cvt.u32.u64 %0, t; }" : "=r"(a) : "l"(p));
    return a;
}
__device__ __forceinline__ void ldsm4(uint32_t* r, uint32_t addr) {
    asm volatile("ldmatrix.sync.aligned.m8n8.x4.shared.b16 {%0,%1,%2,%3}, [%4];"
        : "=r"(r[0]), "=r"(r[1]), "=r"(r[2]), "=r"(r[3]) : "r"(addr));
}
__device__ __forceinline__ void ldsm4t(uint32_t* r, uint32_t addr) {
    asm volatile("ldmatrix.sync.aligned.m8n8.x4.trans.shared.b16 {%0,%1,%2,%3}, [%4];"
        : "=r"(r[0]), "=r"(r[1]), "=r"(r[2]), "=r"(r[3]) : "r"(addr));
}
__device__ __forceinline__ void mma_f16(float& d0, float& d1, float& d2, float& d3,
                                        const uint32_t* a, uint32_t b0, uint32_t b1) {
    asm volatile("mma.sync.aligned.m16n8k16.row.col.f32.f16.f16.f32 "
        "{%0,%1,%2,%3}, {%4,%5,%6,%7}, {%8,%9}, {%0,%1,%2,%3};"
        : "+f"(d0), "+f"(d1), "+f"(d2), "+f"(d3)
        : "r"(a[0]), "r"(a[1]), "r"(a[2]), "r"(a[3]), "r"(b0), "r"(b1));
}
#define CP16(dst, src) asm volatile("cp.async.cg.shared.global [%0], [%1], 16;" :: "r"(dst), "l"(src))
#define CP_COMMIT()    asm volatile("cp.async.commit_group;")
#define CP_WAIT1()     asm volatile("cp.async.wait_group 1;")
#define CP_WAIT0()     asm volatile("cp.async.wait_group 0;")

__device__ __forceinline__ void split_h(float v, __half& h, __half& l) {
    h = __float2half(v);
    l = __float2half(v - __half2float(h));
}
__device__ __forceinline__ float elu1(float v) {
    return v > 0.f ? v + 1.f : __expf(v);
}

// ---------------- conversion kernels ----------------
__global__ void xcat(const float* __restrict__ x) {
    int i = (blockIdx.x * 256 + threadIdx.x) * 4;
    if (i >= MROWS * CDIM) return;
    float4 v = *(const float4*)(x + i);
    int row = i >> 8, col = i & 255;
    __half* d = g_cat + (size_t)row * 512 + col;
    *(__half2*)(d)     = __half2{__float2half(v.x), __float2half(v.y)};
    *(__half2*)(d + 2) = __half2{__float2half(v.z), __float2half(v.w)};
}
__global__ void aconv(const float* __restrict__ s, __half* __restrict__ d, int n) {
    int i = (blockIdx.x * 256 + threadIdx.x) * 4;
    if (i >= n) return;
    float4 v = *(const float4*)(s + i);
    *(__half2*)(d + i)     = __half2{__float2half(v.x), __float2half(v.y)};
    *(__half2*)(d + i + 2) = __half2{__float2half(v.z), __float2half(v.w)};
}
__global__ void wsplit(const float* __restrict__ s, __half* __restrict__ dh,
                       __half* __restrict__ dl, int n) {
    int i = blockIdx.x * 256 + threadIdx.x;
    if (i >= n) return;
    split_h(s[i], dh[i], dl[i]);
}
__global__ void wkvconv(const float* __restrict__ Wk, const float* __restrict__ Wv) {
    int i = blockIdx.x * 256 + threadIdx.x;
    if (i >= 256 * 512) return;
    int k = i >> 9, nn = i & 511;
    float v = (nn < 256) ? Wk[k * 256 + nn] : Wv[k * 256 + nn - 256];
    split_h(v, g_Wkv_h[i], g_Wkv_l[i]);
}
__global__ void zero_kernel() {
    int i = blockIdx.x * blockDim.x + threadIdx.x;
    if (i < NBATCH * HHEADS * DHEAD * DHEAD) g_KV[i] = 0.f;
    if (i < NBATCH * CDIM) g_Ksum[i] = 0.f;
}

// ============ small GEMM: CTA 128x128x32, warp 64x32, 2 CTAs/SM ============
#define SA   40
#define SBs  136
#define A_ST 10240u
#define BsST 8704u
#define STGs 27648u
#define SMSZ_S (3u * STGs)     // 82944

template <int MODE>
__global__ __launch_bounds__(256, 2)
void mma_small(const float* __restrict__ pe)
{
    constexpr int KTOT  = (MODE == MH) ? 512 : 256;
    constexpr int NCOLS = (MODE == MQ) ? 256 : 512;
    constexpr int ASTR  = (MODE == MKV) ? 256 : 512;
    constexpr int S = KTOT / 32;
    extern __shared__ char sm[];
    const uint32_t smb = smem_u32(sm);
    const int tid = threadIdx.x;
    const int wid = tid >> 5, lane = tid & 31;
    const int wm = wid >> 2, wn = wid & 3;
    const int n0 = blockIdx.x * 128;
    const int m0 = blockIdx.y * 128;

    const __half* Bh = (MODE == MQ) ? g_Wq_h : (MODE == MKV) ? g_Wkv_h : g_W1_h;
    const __half* Bl = (MODE == MQ) ? g_Wq_l : (MODE == MKV) ? g_Wkv_l : g_W1_l;
    const __half* A0 = (MODE == MKV) ? g_sb : g_cat;

    const __half* gA0 = A0 + (size_t)(m0 + (tid >> 2)) * ASTR + (tid & 3) * 8;
    const __half* gA1 = gA0 + 64 * ASTR;
    const uint32_t dA0 = (tid >> 2) * 80u + (tid & 3) * 16u;
    const uint32_t dA1 = dA0 + 64u * 80u;
    const ptrdiff_t bdelta = Bl - Bh;
    const __half* gB0 = Bh + (size_t)(tid >> 4) * NCOLS + n0 + (tid & 15) * 8;
    const uint32_t dB0 = (tid >> 4) * 272u + (tid & 15) * 16u;

    auto cpA = [&](int stg) {
        uint32_t base = smb + stg * STGs;
        CP16(base + dA0, gA0);
        CP16(base + dA1, gA1);
        gA0 += 32; gA1 += 32;
    };
    auto cpB = [&](int stg) {
        uint32_t base = smb + stg * STGs + A_ST;
        const __half* g = gB0;
#pragma unroll
        for (int i = 0; i < 2; i++) {
            uint32_t d = base + dB0 + i * (16u * 272u);
            CP16(d, g);
            CP16(d + BsST, g + bdelta);
            g += 16 * NCOLS;
        }
        gB0 += 32 * NCOLS;
    };

    float acc[4][4][4];
#pragma unroll
    for (int a = 0; a < 4; a++)
#pragma unroll
        for (int b = 0; b < 4; b++)
#pragma unroll
            for (int c = 0; c < 4; c++) acc[a][b][c] = 0.f;

    const uint32_t aoffBase = ((wm * 64 + (lane & 15)) * SA + (lane >> 4) * 8) * 2u;
    const uint32_t boffBase = (((lane & 15)) * SBs + wn * 32 + (lane >> 4) * 8) * 2u;

    auto compute = [&](int stg) {
        const uint32_t aB = smb + stg * STGs + aoffBase;
        const uint32_t bH = smb + stg * STGs + A_ST + boffBase;
        const uint32_t bL = bH + BsST;
#pragma unroll
        for (int k16 = 0; k16 < 32; k16 += 16) {
            uint32_t af[4][4], bh[2][4], bl[2][4];
#pragma unroll
            for (int mt = 0; mt < 4; mt++)
                ldsm4(af[mt], aB + (mt * 16 * SA + k16) * 2u);
#pragma unroll
            for (int nt = 0; nt < 2; nt++) {
                uint32_t o = (k16 * SBs + nt * 16) * 2u;
                ldsm4t(bh[nt], bH + o);
                ldsm4t(bl[nt], bL + o);
            }
            // hi phase: 16 HMMA, all distinct accumulators
#pragma unroll
            for (int mt = 0; mt < 4; mt++)
#pragma unroll
                for (int nt = 0; nt < 2; nt++) {
                    float* d0 = acc[mt][nt * 2];
                    float* d1 = acc[mt][nt * 2 + 1];
                    mma_f16(d0[0], d0[1], d0[2], d0[3], af[mt], bh[nt][0], bh[nt][1]);
                    mma_f16(d1[0], d1[1], d1[2], d1[3], af[mt], bh[nt][2], bh[nt][3]);
                }
            // lo phase: same accumulators, 16 ops later
#pragma unroll
            for (int mt = 0; mt < 4; mt++)
#pragma unroll
                for (int nt = 0; nt < 2; nt++) {
                    float* d0 = acc[mt][nt * 2];
                    float* d1 = acc[mt][nt * 2 + 1];
                    mma_f16(d0[0], d0[1], d0[2], d0[3], af[mt], bl[nt][0], bl[nt][1]);
                    mma_f16(d1[0], d1[1], d1[2], d1[3], af[mt], bl[nt][2], bl[nt][3]);
                }
        }
    };

    cpA(0); cpB(0); CP_COMMIT();
    cpA(1); cpB(1); CP_COMMIT();
#pragma unroll 1
    for (int s = 0; s < S; s++) {
        if (s < S - 1) { CP_WAIT1(); } else { CP_WAIT0(); }
        __syncthreads();
        if (s + 2 < S) {
            int stg = (s + 2) % 3;
            cpA(stg); cpB(stg); CP_COMMIT();
        }
        compute(s % 3);
    }

    // ---- epilogue ----
    const int Mbase = m0 + wm * 64;
    const int Nbase = n0 + wn * 32;
    const int rr = lane >> 2;
    const int cc = (lane & 3) * 2;

    float csum[4][2];
    const bool kpath = (MODE == MKV) && (n0 < 256);
    if (kpath) {
#pragma unroll
        for (int a = 0; a < 4; a++) { csum[a][0] = 0.f; csum[a][1] = 0.f; }
        __syncthreads();
        if (tid < 128) ((float*)sm)[tid] = 0.f;
        __syncthreads();
    }

#pragma unroll
    for (int mt = 0; mt < 4; mt++)
#pragma unroll
        for (int n8 = 0; n8 < 4; n8++)
#pragma unroll
            for (int h2 = 0; h2 < 2; h2++) {
                int row = Mbase + mt * 16 + rr + h2 * 8;
                int col = Nbase + n8 * 8 + cc;
                float d0 = acc[mt][n8][2 * h2];
                float d1 = acc[mt][n8][2 * h2 + 1];
                if (MODE == MQ) {
                    float4 pv = *(const float4*)(pe + ((size_t)row * 256 + col) * 2);
                    *(__half2*)(g_Qpos + (size_t)row * 256 + col) = __half2{
                        __float2half(d0 * pv.x - d1 * pv.y),
                        __float2half(d1 * pv.z + d0 * pv.w)};
                    *(__half2*)(g_Qh + (size_t)row * 256 + col) = __half2{
                        __float2half(elu1(d0)), __float2half(elu1(d1))};
                } else if (MODE == MKV) {
                    int pc = kpath ? col : col - 256;
                    float4 pv = *(const float4*)(pe + ((size_t)row * 256 + pc) * 2);
                    float re = d0 * pv.x - d1 * pv.y;
                    float ro = d1 * pv.z + d0 * pv.w;
                    if (kpath) {
                        *(__half2*)(g_Kpos + (size_t)row * 256 + col) = __half2{
                            __float2half(re), __float2half(ro)};
                        csum[n8][0] += elu1(d0);
                        csum[n8][1] += elu1(d1);
                    } else {
                        *(__half2*)(g_Vrot + (size_t)row * 256 + pc) = __half2{
                            __float2half(re), __float2half(ro)};
                    }
                } else {  // MH
                    *(__half2*)(g_hb + (size_t)row * 512 + col) = __half2{
                        __float2half(fmaxf(d0, 0.f)), __float2half(fmaxf(d1, 0.f))};
                }
            }

    if (kpath) {
        float* scs = (float*)sm;
#pragma unroll
        for (int n8 = 0; n8 < 4; n8++) {
            atomicAdd(&scs[wn * 32 + n8 * 8 + cc],     csum[n8][0]);
            atomicAdd(&scs[wn * 32 + n8 * 8 + cc + 1], csum[n8][1]);
        }
        __syncthreads();
        if (tid < 128) {
            int n = m0 / SSEQ;
            atomicAdd(&g_Ksum[n * CDIM + n0 + tid], scs[tid]);
        }
    }
}

// ========= big GEMM: CTA 128x256x32, 16 warps (2x8) of 64x32, LN fused =====
#define SB 264
#define B_ST 16896u
#define STG  44032u
#define SMSZ (3u * STG)        // 132096

template <int MODE>
__global__ __launch_bounds__(512, 1)
void mma_big(const float* __restrict__ lng, const float* __restrict__ lnb,
             const float* __restrict__ xres, float* __restrict__ outx)
{
    constexpr int KTOT  = (MODE == MO) ? 512 : 256;
    constexpr int ASTR  = (MODE == MO) ? 512 : 256;
    constexpr int S = KTOT / 32;
    extern __shared__ char sm[];
    const uint32_t smb = smem_u32(sm);
    const int tid = threadIdx.x;
    const int wid = tid >> 5, lane = tid & 31;
    const int wm = wid >> 3, wn = wid & 7;
    const int m0 = blockIdx.y * 128;

    const __half* Bh = (MODE == MM) ? g_Wm_h : g_W2_h;
    const __half* Bl = (MODE == MM) ? g_Wm_l : g_W2_l;
    const __half* A0 = (MODE == MM) ? g_Qrb : g_hb;

    const __half* gA0 = A0 + (size_t)(m0 + (tid >> 2)) * ASTR + (tid & 3) * 8;
    const uint32_t dA0 = (tid >> 2) * 80u + (tid & 3) * 16u;
    const ptrdiff_t bdelta = Bl - Bh;
    const __half* gB0 = Bh + (size_t)(tid >> 5) * 256 + (tid & 31) * 8;
    const uint32_t dB0 = (tid >> 5) * 528u + (tid & 31) * 16u;

    auto cpA = [&](int stg) {
        CP16(smb + stg * STG + dA0, gA0);
        gA0 += 32;
    };
    auto cpB = [&](int stg) {
        uint32_t base = smb + stg * STG + A_ST;
        const __half* g = gB0;
#pragma unroll
        for (int i = 0; i < 2; i++) {
            uint32_t d = base + dB0 + i * (16u * 528u);
            CP16(d, g);
            CP16(d + B_ST, g + bdelta);
            g += 16 * 256;
        }
        gB0 += 32 * 256;
    };

    float acc[4][4][4];
#pragma unroll
    for (int a = 0; a < 4; a++)
#pragma unroll
        for (int b = 0; b < 4; b++)
#pragma unroll
            for (int c = 0; c < 4; c++) acc[a][b][c] = 0.f;

    const uint32_t aoffBase = ((wm * 64 + (lane & 15)) * SA + (lane >> 4) * 8) * 2u;
    const uint32_t boffBase = (((lane & 15)) * SB + wn * 32 + (lane >> 4) * 8) * 2u;

    auto compute = [&](int stg) {
        const uint32_t aB = smb + stg * STG + aoffBase;
        const uint32_t bH = smb + stg * STG + A_ST + boffBase;
        const uint32_t bL = bH + B_ST;
#pragma unroll
        for (int k16 = 0; k16 < 32; k16 += 16) {
            uint32_t af[4][4], bh[2][4], bl[2][4];
#pragma unroll
            for (int mt = 0; mt < 4; mt++)
                ldsm4(af[mt], aB + (mt * 16 * SA + k16) * 2u);
#pragma unroll
            for (int nt = 0; nt < 2; nt++) {
                uint32_t o = (k16 * SB + nt * 16) * 2u;
                ldsm4t(bh[nt], bH + o);
                ldsm4t(bl[nt], bL + o);
            }
#pragma unroll
            for (int mt = 0; mt < 4; mt++)
#pragma unroll
                for (int nt = 0; nt < 2; nt++) {
                    float* d0 = acc[mt][nt * 2];
                    float* d1 = acc[mt][nt * 2 + 1];
                    mma_f16(d0[0], d0[1], d0[2], d0[3], af[mt], bh[nt][0], bh[nt][1]);
                    mma_f16(d1[0], d1[1], d1[2], d1[3], af[mt], bh[nt][2], bh[nt][3]);
                }
#pragma unroll
            for (int mt = 0; mt < 4; mt++)
#pragma unroll
                for (int nt = 0; nt < 2; nt++) {
                    float* d0 = acc[mt][nt * 2];
                    float* d1 = acc[mt][nt * 2 + 1];
                    mma_f16(d0[0], d0[1], d0[2], d0[3], af[mt], bl[nt][0], bl[nt][1]);
                    mma_f16(d1[0], d1[1], d1[2], d1[3], af[mt], bl[nt][2], bl[nt][3]);
                }
        }
    };

    cpA(0); cpB(0); CP_COMMIT();
    cpA(1); cpB(1); CP_COMMIT();
#pragma unroll 1
    for (int s = 0; s < S; s++) {
        if (s < S - 1) { CP_WAIT1(); } else { CP_WAIT0(); }
        __syncthreads();
        if (s + 2 < S) {
            int stg = (s + 2) % 3;
            cpA(stg); cpB(stg); CP_COMMIT();
        }
        compute(s % 3);
    }

    // ---- fused LayerNorm epilogue ----
    const int Nbase = wn * 32;
    const int rr = lane >> 2;
    const int cc = (lane & 3) * 2;
    float* rs = (float*)sm;
    __syncthreads();
    if (tid < 256) rs[tid] = 0.f;
    __syncthreads();
#pragma unroll
    for (int mt = 0; mt < 4; mt++)
#pragma unroll
        for (int h2 = 0; h2 < 2; h2++) {
            int lrow = wm * 64 + mt * 16 + rr + h2 * 8;
            float s = 0.f, ss = 0.f;
#pragma unroll
            for (int n8 = 0; n8 < 4; n8++) {
                float d0 = acc[mt][n8][2 * h2];
                float d1 = acc[mt][n8][2 * h2 + 1];
                s += d0 + d1;
                ss += d0 * d0 + d1 * d1;
            }
            atomicAdd(&rs[lrow], s);
            atomicAdd(&rs[128 + lrow], ss);
        }
    __syncthreads();
#pragma unroll
    for (int mt = 0; mt < 4; mt++)
#pragma unroll
        for (int h2 = 0; h2 < 2; h2++) {
            int lrow = wm * 64 + mt * 16 + rr + h2 * 8;
            int row = m0 + lrow;
            float mean = rs[lrow] * (1.f / 256.f);
            float var  = rs[128 + lrow] * (1.f / 256.f) - mean * mean;
            float rstd = rsqrtf(var + 1e-5f);
#pragma unroll
            for (int n8 = 0; n8 < 4; n8++) {
                int col = Nbase + n8 * 8 + cc;
                float v0 = (acc[mt][n8][2 * h2]     - mean) * rstd * lng[col] + lnb[col];
                float v1 = (acc[mt][n8][2 * h2 + 1] - mean) * rstd * lng[col + 1] + lnb[col + 1];
                if (MODE == MM) {
                    *(__half2*)(g_cat + (size_t)row * 512 + 256 + col) = __half2{
                        __float2half(v0), __float2half(v1)};
                } else {
                    const float* xr = xres + (size_t)row * 256 + col;
                    *(float2*)(outx + (size_t)row * 256 + col) =
                        make_float2(v0 + xr[0], v1 + xr[1]);
                }
            }
        }
}

// ---------------- KV einsum ----------------
__global__ __launch_bounds__(256) void kv_kernel() {
    const int nh = blockIdx.x;
    const int n = nh / HHEADS, h = nh % HHEADS;
    const int s0 = blockIdx.y * (SSEQ / 8);
    __shared__ float sK[16][DHEAD];
    __shared__ float sV[16][DHEAD];
    const int t = threadIdx.x;
    const int d = t >> 3, vb = (t & 7) * 4;
    float a0 = 0.f, a1 = 0.f, a2 = 0.f, a3 = 0.f;
    for (int sc = 0; sc < SSEQ / 8; sc += 16) {
#pragma unroll
        for (int rep = 0; rep < 2; rep++) {
            int idx = t + rep * 256;
            int sr = idx >> 5, c = idx & 31;
            int off = (n * SSEQ + s0 + sc + sr) * CDIM + h * DHEAD + c;
            sK[sr][c] = __half2float(g_Kpos[off]);
            sV[sr][c] = __half2float(g_Vrot[off]);
        }
        __syncthreads();
#pragma unroll
        for (int sr = 0; sr < 16; sr++) {
            float kd = sK[sr][d];
            float4 v = *(const float4*)&sV[sr][vb];
            a0 += kd * v.x; a1 += kd * v.y; a2 += kd * v.z; a3 += kd * v.w;
        }
        __syncthreads();
    }
    float* dst = &g_KV[((n * HHEADS + h) * DHEAD + d) * DHEAD + vb];
    atomicAdd(dst + 0, a0); atomicAdd(dst + 1, a1);
    atomicAdd(dst + 2, a2); atomicAdd(dst + 3, a3);
}

// ------- queried -------
__global__ __launch_bounds__(256) void queried_kernel() {
    const int n  = blockIdx.x >> 5;
    const int l0 = (blockIdx.x & 31) * 128;
    const int h = threadIdx.x >> 5, lane = threadIdx.x & 31;
    float kvreg[32];
    const float* kvb = &g_KV[(n * HHEADS + h) * DHEAD * DHEAD];
#pragma unroll
    for (int dd = 0; dd < 32; dd++) kvreg[dd] = kvb[dd * 32 + lane];
    const float ks = g_Ksum[n * CDIM + h * 32 + lane];
#pragma unroll 2
    for (int r = 0; r < 128; r++) {
        size_t base = ((size_t)(n * LSEQ + l0 + r)) * CDIM + h * 32;
        float q  = __half2float(g_Qh[base + lane]);
        float qp = __half2float(g_Qpos[base + lane]);
        float p = q * ks;
#pragma unroll
        for (int o = 16; o; o >>= 1) p += __shfl_xor_sync(0xffffffffu, p, o);
        float z = 1.0f / (p + 1e-6f);
        float s1 = 0.f;
#pragma unroll
        for (int dd = 0; dd < 32; dd++)
            s1 += __shfl_sync(0xffffffffu, qp, dd) * kvreg[dd];
        g_Qrb[base + lane] = __float2half(s1 * z);
    }
}

// ---------------- launch ----------------
extern "C" void kernel_launch(void* const* d_in, const int* in_sizes, int n_in,
                              void* d_out, int out_size)
{
    const float* x      = (const float*)d_in[0];
    const float* source = (const float*)d_in[1];
    const float* x_pe   = (const float*)d_in[2];
    const float* s_pe   = (const float*)d_in[3];
    const float* Wq     = (const float*)d_in[4];
    const float* Wk     = (const float*)d_in[5];
    const float* Wv     = (const float*)d_in[6];
    const float* Wm     = (const float*)d_in[7];
    const float* W1     = (const float*)d_in[8];
    const float* W2     = (const float*)d_in[9];
    const float* ln1_g  = (const float*)d_in[10];
    const float* ln1_b  = (const float*)d_in[11];
    const float* ln2_g  = (const float*)d_in[12];
    const float* ln2_b  = (const float*)d_in[13];
    float* out = (float*)d_out;

    cudaFuncSetAttribute(mma_small<MQ>,  cudaFuncAttributeMaxDynamicSharedMemorySize, SMSZ_S);
    cudaFuncSetAttribute(mma_small<MKV>, cudaFuncAttributeMaxDynamicSharedMemorySize, SMSZ_S);
    cudaFuncSetAttribute(mma_small<MH>,  cudaFuncAttributeMaxDynamicSharedMemorySize, SMSZ_S);
    cudaFuncSetAttribute(mma_big<MM>,    cudaFuncAttributeMaxDynamicSharedMemorySize, SMSZ);
    cudaFuncSetAttribute(mma_big<MO>,    cudaFuncAttributeMaxDynamicSharedMemorySize, SMSZ);

    __half *sb, *wqh, *wql, *wmh, *wml, *w1h, *w1l, *w2h, *w2l;
    cudaGetSymbolAddress((void**)&sb, g_sb);
    cudaGetSymbolAddress((void**)&wqh, g_Wq_h); cudaGetSymbolAddress((void**)&wql, g_Wq_l);
    cudaGetSymbolAddress((void**)&wmh, g_Wm_h); cudaGetSymbolAddress((void**)&wml, g_Wm_l);
    cudaGetSymbolAddress((void**)&w1h, g_W1_h); cudaGetSymbolAddress((void**)&w1l, g_W1_l);
    cudaGetSymbolAddress((void**)&w2h, g_W2_h); cudaGetSymbolAddress((void**)&w2l, g_W2_l);

    xcat<<<MROWS * CDIM / 1024, 256>>>(x);
    wsplit<<<256 * 256 / 256, 256>>>(Wq, wqh, wql, 256 * 256);
    zero_kernel<<<256, 256>>>();
    mma_small<MQ><<<dim3(2, MROWS / 128), 256, SMSZ_S>>>(x_pe);
    aconv<<<MROWS * CDIM / 1024, 256>>>(source, sb, MROWS * CDIM);
    wkvconv<<<256 * 512 / 256, 256>>>(Wk, Wv);
    mma_small<MKV><<<dim3(4, MROWS / 128), 256, SMSZ_S>>>(s_pe);

    kv_kernel<<<dim3(NBATCH * HHEADS, 8), 256>>>();
    queried_kernel<<<NBATCH * (LSEQ / 128), 256>>>();

    wsplit<<<256 * 256 / 256, 256>>>(Wm, wmh, wml, 256 * 256);
    mma_big<MM><<<dim3(1, MROWS / 128), 512, SMSZ>>>(ln1_g, ln1_b, nullptr, nullptr);

    wsplit<<<512 * 512 / 256, 256>>>(W1, w1h, w1l, 512 * 512);
    mma_small<MH><<<dim3(4, MROWS / 128), 256, SMSZ_S>>>(nullptr);
    wsplit<<<512 * 256 / 256, 256>>>(W2, w2h, w2l, 512 * 256);
    mma_big<MO><<<dim3(1, MROWS / 128), 512, SMSZ>>>(ln2_g, ln2_b, x, out);
}

// round 16
// speedup vs baseline: 1.1894x; 1.1878x over previous
#include <cuda_runtime.h>
#include <cuda_fp16.h>
#include <math.h>
#include <cstdint>

#define NBATCH 8
#define LSEQ   4096
#define SSEQ   4096
#define CDIM   256
#define HHEADS 8
#define DHEAD  32
#define MROWS  (NBATCH * LSEQ)

#define MQ  0
#define MKV 1
#define MM  2
#define MH  3
#define MO  4

__device__ float g_Ksum[NBATCH * CDIM];
__device__ float g_KV  [NBATCH * HHEADS * DHEAD * DHEAD];

__device__ __align__(256) __half g_Qh   [MROWS * CDIM];
__device__ __align__(256) __half g_Qpos [MROWS * CDIM];
__device__ __align__(256) __half g_Kpos [MROWS * CDIM];
__device__ __align__(256) __half g_Vrot [MROWS * CDIM];
__device__ __align__(256) __half g_cat  [MROWS * 512];   // [x | msg]
__device__ __align__(256) __half g_sb   [MROWS * CDIM];
__device__ __align__(256) __half g_Qrb  [MROWS * CDIM];
__device__ __align__(256) __half g_hb   [MROWS * 512];
// weights: single fp16
__device__ __align__(256) __half g_Wq  [256 * 256];
__device__ __align__(256) __half g_Wkv [256 * 512];
__device__ __align__(256) __half g_Wm  [256 * 256];
__device__ __align__(256) __half g_W1  [512 * 512];
__device__ __align__(256) __half g_W2  [512 * 256];

__device__ __forceinline__ uint32_t smem_u32(const void* p) {
    uint32_t a;
    asm("{ .reg .u64 t; cvta.to.shared.u64 t, %1; cvt.u32.u64 %0, t; }" : "=r"(a) : "l"(p));
    return a;
}
__device__ __forceinline__ void ldsm4(uint32_t* r, uint32_t addr) {
    asm volatile("ldmatrix.sync.aligned.m8n8.x4.shared.b16 {%0,%1,%2,%3}, [%4];"
        : "=r"(r[0]), "=r"(r[1]), "=r"(r[2]), "=r"(r[3]) : "r"(addr));
}
__device__ __forceinline__ void ldsm4t(uint32_t* r, uint32_t addr) {
    asm volatile("ldmatrix.sync.aligned.m8n8.x4.trans.shared.b16 {%0,%1,%2,%3}, [%4];"
        : "=r"(r[0]), "=r"(r[1]), "=r"(r[2]), "=r"(r[3]) : "r"(addr));
}
__device__ __forceinline__ void mma_f16(float& d0, float& d1, float& d2, float& d3,
                                        const uint32_t* a, uint32_t b0, uint32_t b1) {
    asm volatile("mma.sync.aligned.m16n8k16.row.col.f32.f16.f16.f32 "
        "{%0,%1,%2,%3}, {%4,%5,%6,%7}, {%8,%9}, {%0,%1,%2,%3};"
        : "+f"(d0), "+f"(d1), "+f"(d2), "+f"(d3)
        : "r"(a[0]), "r"(a[1]), "r"(a[2]), "r"(a[3]), "r"(b0), "r"(b1));
}
#define CP16(dst, src) asm volatile("cp.async.cg.shared.global [%0], [%1], 16;" :: "r"(dst), "l"(src))
#define CP_COMMIT()    asm volatile("cp.async.commit_group;")
#define CP_WAIT1()     asm volatile("cp.async.wait_group 1;")
#define CP_WAIT0()     asm volatile("cp.async.wait_group 0;")

__device__ __forceinline__ float elu1(float v) {
    return v > 0.f ? v + 1.f : __expf(v);
}

// ---------------- conversion kernels ----------------
__global__ void xcat(const float* __restrict__ x) {
    int i = (blockIdx.x * 256 + threadIdx.x) * 4;
    if (i >= MROWS * CDIM) return;
    float4 v = *(const float4*)(x + i);
    int row = i >> 8, col = i & 255;
    __half* d = g_cat + (size_t)row * 512 + col;
    *(__half2*)(d)     = __half2{__float2half(v.x), __float2half(v.y)};
    *(__half2*)(d + 2) = __half2{__float2half(v.z), __float2half(v.w)};
}
__global__ void aconv(const float* __restrict__ s, __half* __restrict__ d, int n) {
    int i = (blockIdx.x * 256 + threadIdx.x) * 4;
    if (i >= n) return;
    float4 v = *(const float4*)(s + i);
    *(__half2*)(d + i)     = __half2{__float2half(v.x), __float2half(v.y)};
    *(__half2*)(d + i + 2) = __half2{__float2half(v.z), __float2half(v.w)};
}
__global__ void wkvconv(const float* __restrict__ Wk, const float* __restrict__ Wv) {
    int i = blockIdx.x * 256 + threadIdx.x;
    if (i >= 256 * 512) return;
    int k = i >> 9, nn = i & 511;
    float v = (nn < 256) ? Wk[k * 256 + nn] : Wv[k * 256 + nn - 256];
    g_Wkv[i] = __float2half(v);
}
__global__ void zero_kernel() {
    int i = blockIdx.x * blockDim.x + threadIdx.x;
    if (i < NBATCH * HHEADS * DHEAD * DHEAD) g_KV[i] = 0.f;
    if (i < NBATCH * CDIM) g_Ksum[i] = 0.f;
}

// ============ small GEMM: CTA 128x128x32, warp 64x32, 2 CTAs/SM ============
#define SA   40
#define SBs  136
#define A_ST 10240u
#define BsST 8704u
#define STGs 18944u            // A_ST + BsST
#define SMSZ_S (3u * STGs)     // 56832

template <int MODE>
__global__ __launch_bounds__(256, 2)
void mma_small(const float* __restrict__ pe)
{
    constexpr int KTOT  = (MODE == MH) ? 512 : 256;
    constexpr int NCOLS = (MODE == MQ) ? 256 : 512;
    constexpr int ASTR  = (MODE == MKV) ? 256 : 512;
    constexpr int S = KTOT / 32;
    extern __shared__ char sm[];
    const uint32_t smb = smem_u32(sm);
    const int tid = threadIdx.x;
    const int wid = tid >> 5, lane = tid & 31;
    const int wm = wid >> 2, wn = wid & 3;
    const int n0 = blockIdx.x * 128;
    const int m0 = blockIdx.y * 128;

    const __half* B = (MODE == MQ) ? g_Wq : (MODE == MKV) ? g_Wkv : g_W1;
    const __half* A0 = (MODE == MKV) ? g_sb : g_cat;

    const __half* gA0 = A0 + (size_t)(m0 + (tid >> 2)) * ASTR + (tid & 3) * 8;
    const __half* gA1 = gA0 + 64 * ASTR;
    const uint32_t dA0 = (tid >> 2) * 80u + (tid & 3) * 16u;
    const uint32_t dA1 = dA0 + 64u * 80u;
    const __half* gB0 = B + (size_t)(tid >> 4) * NCOLS + n0 + (tid & 15) * 8;
    const uint32_t dB0 = (tid >> 4) * 272u + (tid & 15) * 16u;

    auto cpA = [&](int stg) {
        uint32_t base = smb + stg * STGs;
        CP16(base + dA0, gA0);
        CP16(base + dA1, gA1);
        gA0 += 32; gA1 += 32;
    };
    auto cpB = [&](int stg) {
        uint32_t base = smb + stg * STGs + A_ST;
        const __half* g = gB0;
#pragma unroll
        for (int i = 0; i < 2; i++) {
            CP16(base + dB0 + i * (16u * 272u), g);
            g += 16 * NCOLS;
        }
        gB0 += 32 * NCOLS;
    };

    float acc[4][4][4];
#pragma unroll
    for (int a = 0; a < 4; a++)
#pragma unroll
        for (int b = 0; b < 4; b++)
#pragma unroll
            for (int c = 0; c < 4; c++) acc[a][b][c] = 0.f;

    const uint32_t aoffBase = ((wm * 64 + (lane & 15)) * SA + (lane >> 4) * 8) * 2u;
    const uint32_t boffBase = (((lane & 15)) * SBs + wn * 32 + (lane >> 4) * 8) * 2u;

    auto compute = [&](int stg) {
        const uint32_t aB = smb + stg * STGs + aoffBase;
        const uint32_t bB = smb + stg * STGs + A_ST + boffBase;
#pragma unroll
        for (int k16 = 0; k16 < 32; k16 += 16) {
            uint32_t af[4][4], bf[2][4];
#pragma unroll
            for (int mt = 0; mt < 4; mt++)
                ldsm4(af[mt], aB + (mt * 16 * SA + k16) * 2u);
#pragma unroll
            for (int nt = 0; nt < 2; nt++)
                ldsm4t(bf[nt], bB + (k16 * SBs + nt * 16) * 2u);
#pragma unroll
            for (int mt = 0; mt < 4; mt++)
#pragma unroll
                for (int nt = 0; nt < 2; nt++) {
                    float* d0 = acc[mt][nt * 2];
                    float* d1 = acc[mt][nt * 2 + 1];
                    mma_f16(d0[0], d0[1], d0[2], d0[3], af[mt], bf[nt][0], bf[nt][1]);
                    mma_f16(d1[0], d1[1], d1[2], d1[3], af[mt], bf[nt][2], bf[nt][3]);
                }
        }
    };

    cpA(0); cpB(0); CP_COMMIT();
    cpA(1); cpB(1); CP_COMMIT();
#pragma unroll 1
    for (int s = 0; s < S; s++) {
        if (s < S - 1) { CP_WAIT1(); } else { CP_WAIT0(); }
        __syncthreads();
        if (s + 2 < S) {
            int stg = (s + 2) % 3;
            cpA(stg); cpB(stg); CP_COMMIT();
        }
        compute(s % 3);
    }

    // ---- epilogue ----
    const int Mbase = m0 + wm * 64;
    const int Nbase = n0 + wn * 32;
    const int rr = lane >> 2;
    const int cc = (lane & 3) * 2;

    float csum[4][2];
    const bool kpath = (MODE == MKV) && (n0 < 256);
    if (kpath) {
#pragma unroll
        for (int a = 0; a < 4; a++) { csum[a][0] = 0.f; csum[a][1] = 0.f; }
        __syncthreads();
        if (tid < 128) ((float*)sm)[tid] = 0.f;
        __syncthreads();
    }

#pragma unroll
    for (int mt = 0; mt < 4; mt++)
#pragma unroll
        for (int n8 = 0; n8 < 4; n8++)
#pragma unroll
            for (int h2 = 0; h2 < 2; h2++) {
                int row = Mbase + mt * 16 + rr + h2 * 8;
                int col = Nbase + n8 * 8 + cc;
                float d0 = acc[mt][n8][2 * h2];
                float d1 = acc[mt][n8][2 * h2 + 1];
                if (MODE == MQ) {
                    float4 pv = *(const float4*)(pe + ((size_t)row * 256 + col) * 2);
                    *(__half2*)(g_Qpos + (size_t)row * 256 + col) = __half2{
                        __float2half(d0 * pv.x - d1 * pv.y),
                        __float2half(d1 * pv.z + d0 * pv.w)};
                    *(__half2*)(g_Qh + (size_t)row * 256 + col) = __half2{
                        __float2half(elu1(d0)), __float2half(elu1(d1))};
                } else if (MODE == MKV) {
                    int pc = kpath ? col : col - 256;
                    float4 pv = *(const float4*)(pe + ((size_t)row * 256 + pc) * 2);
                    float re = d0 * pv.x - d1 * pv.y;
                    float ro = d1 * pv.z + d0 * pv.w;
                    if (kpath) {
                        *(__half2*)(g_Kpos + (size_t)row * 256 + col) = __half2{
                            __float2half(re), __float2half(ro)};
                        csum[n8][0] += elu1(d0);
                        csum[n8][1] += elu1(d1);
                    } else {
                        *(__half2*)(g_Vrot + (size_t)row * 256 + pc) = __half2{
                            __float2half(re), __float2half(ro)};
                    }
                } else {  // MH
                    *(__half2*)(g_hb + (size_t)row * 512 + col) = __half2{
                        __float2half(fmaxf(d0, 0.f)), __float2half(fmaxf(d1, 0.f))};
                }
            }

    if (kpath) {
        float* scs = (float*)sm;
#pragma unroll
        for (int n8 = 0; n8 < 4; n8++) {
            atomicAdd(&scs[wn * 32 + n8 * 8 + cc],     csum[n8][0]);
            atomicAdd(&scs[wn * 32 + n8 * 8 + cc + 1], csum[n8][1]);
        }
        __syncthreads();
        if (tid < 128) {
            int n = m0 / SSEQ;
            atomicAdd(&g_Ksum[n * CDIM + n0 + tid], scs[tid]);
        }
    }
}

// ========= big GEMM: CTA 128x256x32, 16 warps (2x8) of 64x32, LN fused =====
#define SB 264
#define B_ST 16896u
#define STG  27136u            // A_ST + B_ST
#define SMSZ (3u * STG)        // 81408

template <int MODE>
__global__ __launch_bounds__(512, 1)
void mma_big(const float* __restrict__ lng, const float* __restrict__ lnb,
             const float* __restrict__ xres, float* __restrict__ outx)
{
    constexpr int KTOT  = (MODE == MO) ? 512 : 256;
    constexpr int ASTR  = (MODE == MO) ? 512 : 256;
    constexpr int S = KTOT / 32;
    extern __shared__ char sm[];
    const uint32_t smb = smem_u32(sm);
    const int tid = threadIdx.x;
    const int wid = tid >> 5, lane = tid & 31;
    const int wm = wid >> 3, wn = wid & 7;
    const int m0 = blockIdx.y * 128;

    const __half* B = (MODE == MM) ? g_Wm : g_W2;
    const __half* A0 = (MODE == MM) ? g_Qrb : g_hb;

    const __half* gA0 = A0 + (size_t)(m0 + (tid >> 2)) * ASTR + (tid & 3) * 8;
    const uint32_t dA0 = (tid >> 2) * 80u + (tid & 3) * 16u;
    const __half* gB0 = B + (size_t)(tid >> 5) * 256 + (tid & 31) * 8;
    const uint32_t dB0 = (tid >> 5) * 528u + (tid & 31) * 16u;

    auto cpA = [&](int stg) {
        CP16(smb + stg * STG + dA0, gA0);
        gA0 += 32;
    };
    auto cpB = [&](int stg) {
        uint32_t base = smb + stg * STG + A_ST;
        const __half* g = gB0;
#pragma unroll
        for (int i = 0; i < 2; i++) {
            CP16(base + dB0 + i * (16u * 528u), g);
            g += 16 * 256;
        }
        gB0 += 32 * 256;
    };

    float acc[4][4][4];
#pragma unroll
    for (int a = 0; a < 4; a++)
#pragma unroll
        for (int b = 0; b < 4; b++)
#pragma unroll
            for (int c = 0; c < 4; c++) acc[a][b][c] = 0.f;

    const uint32_t aoffBase = ((wm * 64 + (lane & 15)) * SA + (lane >> 4) * 8) * 2u;
    const uint32_t boffBase = (((lane & 15)) * SB + wn * 32 + (lane >> 4) * 8) * 2u;

    auto compute = [&](int stg) {
        const uint32_t aB = smb + stg * STG + aoffBase;
        const uint32_t bB = smb + stg * STG + A_ST + boffBase;
#pragma unroll
        for (int k16 = 0; k16 < 32; k16 += 16) {
            uint32_t af[4][4], bf[2][4];
#pragma unroll
            for (int mt = 0; mt < 4; mt++)
                ldsm4(af[mt], aB + (mt * 16 * SA + k16) * 2u);
#pragma unroll
            for (int nt = 0; nt < 2; nt++)
                ldsm4t(bf[nt], bB + (k16 * SB + nt * 16) * 2u);
#pragma unroll
            for (int mt = 0; mt < 4; mt++)
#pragma unroll
                for (int nt = 0; nt < 2; nt++) {
                    float* d0 = acc[mt][nt * 2];
                    float* d1 = acc[mt][nt * 2 + 1];
                    mma_f16(d0[0], d0[1], d0[2], d0[3], af[mt], bf[nt][0], bf[nt][1]);
                    mma_f16(d1[0], d1[1], d1[2], d1[3], af[mt], bf[nt][2], bf[nt][3]);
                }
        }
    };

    cpA(0); cpB(0); CP_COMMIT();
    cpA(1); cpB(1); CP_COMMIT();
#pragma unroll 1
    for (int s = 0; s < S; s++) {
        if (s < S - 1) { CP_WAIT1(); } else { CP_WAIT0(); }
        __syncthreads();
        if (s + 2 < S) {
            int stg = (s + 2) % 3;
            cpA(stg); cpB(stg); CP_COMMIT();
        }
        compute(s % 3);
    }

    // ---- fused LayerNorm epilogue ----
    const int Nbase = wn * 32;
    const int rr = lane >> 2;
    const int cc = (lane & 3) * 2;
    float* rs = (float*)sm;
    __syncthreads();
    if (tid < 256) rs[tid] = 0.f;
    __syncthreads();
#pragma unroll
    for (int mt = 0; mt < 4; mt++)
#pragma unroll
        for (int h2 = 0; h2 < 2; h2++) {
            int lrow = wm * 64 + mt * 16 + rr + h2 * 8;
            float s = 0.f, ss = 0.f;
#pragma unroll
            for (int n8 = 0; n8 < 4; n8++) {
                float d0 = acc[mt][n8][2 * h2];
                float d1 = acc[mt][n8][2 * h2 + 1];
                s += d0 + d1;
                ss += d0 * d0 + d1 * d1;
            }
            atomicAdd(&rs[lrow], s);
            atomicAdd(&rs[128 + lrow], ss);
        }
    __syncthreads();
#pragma unroll
    for (int mt = 0; mt < 4; mt++)
#pragma unroll
        for (int h2 = 0; h2 < 2; h2++) {
            int lrow = wm * 64 + mt * 16 + rr + h2 * 8;
            int row = m0 + lrow;
            float mean = rs[lrow] * (1.f / 256.f);
            float var  = rs[128 + lrow] * (1.f / 256.f) - mean * mean;
            float rstd = rsqrtf(var + 1e-5f);
#pragma unroll
            for (int n8 = 0; n8 < 4; n8++) {
                int col = Nbase + n8 * 8 + cc;
                float v0 = (acc[mt][n8][2 * h2]     - mean) * rstd * lng[col] + lnb[col];
                float v1 = (acc[mt][n8][2 * h2 + 1] - mean) * rstd * lng[col + 1] + lnb[col + 1];
                if (MODE == MM) {
                    *(__half2*)(g_cat + (size_t)row * 512 + 256 + col) = __half2{
                        __float2half(v0), __float2half(v1)};
                } else {
                    const float* xr = xres + (size_t)row * 256 + col;
                    *(float2*)(outx + (size_t)row * 256 + col) =
                        make_float2(v0 + xr[0], v1 + xr[1]);
                }
            }
        }
}

// ---------------- KV einsum ----------------
__global__ __launch_bounds__(256) void kv_kernel() {
    const int nh = blockIdx.x;
    const int n = nh / HHEADS, h = nh % HHEADS;
    const int s0 = blockIdx.y * (SSEQ / 8);
    __shared__ float sK[16][DHEAD];
    __shared__ float sV[16][DHEAD];
    const int t = threadIdx.x;
    const int d = t >> 3, vb = (t & 7) * 4;
    float a0 = 0.f, a1 = 0.f, a2 = 0.f, a3 = 0.f;
    for (int sc = 0; sc < SSEQ / 8; sc += 16) {
#pragma unroll
        for (int rep = 0; rep < 2; rep++) {
            int idx = t + rep * 256;
            int sr = idx >> 5, c = idx & 31;
            int off = (n * SSEQ + s0 + sc + sr) * CDIM + h * DHEAD + c;
            sK[sr][c] = __half2float(g_Kpos[off]);
            sV[sr][c] = __half2float(g_Vrot[off]);
        }
        __syncthreads();
#pragma unroll
        for (int sr = 0; sr < 16; sr++) {
            float kd = sK[sr][d];
            float4 v = *(const float4*)&sV[sr][vb];
            a0 += kd * v.x; a1 += kd * v.y; a2 += kd * v.z; a3 += kd * v.w;
        }
        __syncthreads();
    }
    float* dst = &g_KV[((n * HHEADS + h) * DHEAD + d) * DHEAD + vb];
    atomicAdd(dst + 0, a0); atomicAdd(dst + 1, a1);
    atomicAdd(dst + 2, a2); atomicAdd(dst + 3, a3);
}

// ------- queried -------
__global__ __launch_bounds__(256) void queried_kernel() {
    const int n  = blockIdx.x >> 5;
    const int l0 = (blockIdx.x & 31) * 128;
    const int h = threadIdx.x >> 5, lane = threadIdx.x & 31;
    float kvreg[32];
    const float* kvb = &g_KV[(n * HHEADS + h) * DHEAD * DHEAD];
#pragma unroll
    for (int dd = 0; dd < 32; dd++) kvreg[dd] = kvb[dd * 32 + lane];
    const float ks = g_Ksum[n * CDIM + h * 32 + lane];
#pragma unroll 2
    for (int r = 0; r < 128; r++) {
        size_t base = ((size_t)(n * LSEQ + l0 + r)) * CDIM + h * 32;
        float q  = __half2float(g_Qh[base + lane]);
        float qp = __half2float(g_Qpos[base + lane]);
        float p = q * ks;
#pragma unroll
        for (int o = 16; o; o >>= 1) p += __shfl_xor_sync(0xffffffffu, p, o);
        float z = 1.0f / (p + 1e-6f);
        float s1 = 0.f;
#pragma unroll
        for (int dd = 0; dd < 32; dd++)
            s1 += __shfl_sync(0xffffffffu, qp, dd) * kvreg[dd];
        g_Qrb[base + lane] = __float2half(s1 * z);
    }
}

// ---------------- launch ----------------
extern "C" void kernel_launch(void* const* d_in, const int* in_sizes, int n_in,
                              void* d_out, int out_size)
{
    const float* x      = (const float*)d_in[0];
    const float* source = (const float*)d_in[1];
    const float* x_pe   = (const float*)d_in[2];
    const float* s_pe   = (const float*)d_in[3];
    const float* Wq     = (const float*)d_in[4];
    const float* Wk     = (const float*)d_in[5];
    const float* Wv     = (const float*)d_in[6];
    const float* Wm     = (const float*)d_in[7];
    const float* W1     = (const float*)d_in[8];
    const float* W2     = (const float*)d_in[9];
    const float* ln1_g  = (const float*)d_in[10];
    const float* ln1_b  = (const float*)d_in[11];
    const float* ln2_g  = (const float*)d_in[12];
    const float* ln2_b  = (const float*)d_in[13];
    float* out = (float*)d_out;

    cudaFuncSetAttribute(mma_small<MQ>,  cudaFuncAttributeMaxDynamicSharedMemorySize, SMSZ_S);
    cudaFuncSetAttribute(mma_small<MKV>, cudaFuncAttributeMaxDynamicSharedMemorySize, SMSZ_S);
    cudaFuncSetAttribute(mma_small<MH>,  cudaFuncAttributeMaxDynamicSharedMemorySize, SMSZ_S);
    cudaFuncSetAttribute(mma_big<MM>,    cudaFuncAttributeMaxDynamicSharedMemorySize, SMSZ);
    cudaFuncSetAttribute(mma_big<MO>,    cudaFuncAttributeMaxDynamicSharedMemorySize, SMSZ);

    __half *sb, *wq, *wm, *w1, *w2;
    cudaGetSymbolAddress((void**)&sb, g_sb);
    cudaGetSymbolAddress((void**)&wq, g_Wq);
    cudaGetSymbolAddress((void**)&wm, g_Wm);
    cudaGetSymbolAddress((void**)&w1, g_W1);
    cudaGetSymbolAddress((void**)&w2, g_W2);

    xcat<<<MROWS * CDIM / 1024, 256>>>(x);
    aconv<<<256 * 256 / 1024, 256>>>(Wq, wq, 256 * 256);
    zero_kernel<<<256, 256>>>();
    mma_small<MQ><<<dim3(2, MROWS / 128), 256, SMSZ_S>>>(x_pe);
    aconv<<<MROWS * CDIM / 1024, 256>>>(source, sb, MROWS * CDIM);
    wkvconv<<<256 * 512 / 256, 256>>>(Wk, Wv);
    mma_small<MKV><<<dim3(4, MROWS / 128), 256, SMSZ_S>>>(s_pe);

    kv_kernel<<<dim3(NBATCH * HHEADS, 8), 256>>>();
    queried_kernel<<<NBATCH * (LSEQ / 128), 256>>>();

    aconv<<<256 * 256 / 1024, 256>>>(Wm, wm, 256 * 256);
    mma_big<MM><<<dim3(1, MROWS / 128), 512, SMSZ>>>(ln1_g, ln1_b, nullptr, nullptr);

    aconv<<<512 * 512 / 1024, 256>>>(W1, w1, 512 * 512);
    mma_small<MH><<<dim3(4, MROWS / 128), 256, SMSZ_S>>>(nullptr);
    aconv<<<512 * 256 / 1024, 256>>>(W2, w2, 512 * 256);
    mma_big<MO><<<dim3(1, MROWS / 128), 512, SMSZ>>>(ln2_g, ln2_b, x, out);
}